// round 11
// baseline (speedup 1.0000x reference)
#include <cuda_runtime.h>
#include <cuda_fp16.h>
#include <cuda_bf16.h>
#include <mma.h>

using namespace nvcuda;

// Problem constants
#define BB 16
#define NN 512
#define HH 16
#define DK 64
#define DM 1024
#define MTOT (BB * NN)   // 8192

// Scratch (allocation-free rule: __device__ globals)
__device__ __half g_q[BB * HH * NN * DK];
__device__ __half g_k[BB * HH * NN * DK];
__device__ __half g_v[BB * HH * NN * DK];
__device__ float  g_ctx[MTOT * DM];

struct QKVArgs {
    const float* X[3];
    const float* W[3];
    const float* bv[3];
    __half*      Y[3];
};

// ---------------------------------------------------------------------------
// Projection GEMM core: Y = X @ W^T + bias, fp16 HMMA m16n16k16.
// Block tile 128x256, 8 warps (2m x 4n), warp tile 64x64 (4x4 frags).
// K-chunk 16 (one k-step), double-buffered smem, pad 24 halves (48B row
// stride -> LDSM conflict-free). b-frags resident, a-frags streamed:
// 8 fragment loads per 16 MMAs (was 6 per 8) -> 33% less LDS traffic.
// ---------------------------------------------------------------------------
#define APAD 24
#define ABUF (128 * APAD)            // halves
#define BBUF (256 * APAD)
#define BUFSZ (ABUF + BBUF)          // 9216 halves per buffer

template <bool SPLIT, typename YT>
__device__ __forceinline__ void proj_body(
    const float* __restrict__ X, const float* __restrict__ W,
    const float* __restrict__ bvec, YT* __restrict__ Y,
    int mBase, int nBase, __half* sm)
{
    const int tid = threadIdx.x;
    const int warp = tid >> 5;
    const int lane = tid & 31;
    const int wm = warp & 1;       // m strip of 64
    const int wn = warp >> 1;      // n strip of 64 (0..3)

    wmma::fragment<wmma::accumulator, 16, 16, 16, float> acc[4][4];
#pragma unroll
    for (int i = 0; i < 4; i++)
#pragma unroll
        for (int j = 0; j < 4; j++) wmma::fill_fragment(acc[i][j], 0.0f);

    float4 ra[2], rbw[4];
    const int arow = tid >> 2;           // 0..63  (x2 strips of 64)
    const int brow = tid >> 2;           // reuse; B covers 256 rows in 4 strips
    const int c4 = (tid & 3) * 4;        // 0,4,8,12

#define LD_CHUNK(K0)                                                                   \
    {                                                                                  \
        _Pragma("unroll")                                                              \
        for (int p = 0; p < 2; p++)                                                    \
            ra[p] = *((const float4*)&X[(size_t)(mBase + arow + p * 64) * DM + (K0) + c4]); \
        _Pragma("unroll")                                                              \
        for (int p = 0; p < 4; p++)                                                    \
            rbw[p] = *((const float4*)&W[(size_t)(nBase + brow + p * 64) * DM + (K0) + c4]); \
    }

#define ST_CHUNK(NB)                                                                   \
    {                                                                                  \
        __half* As_ = sm + (NB) * BUFSZ;                                               \
        __half* Bs_ = As_ + ABUF;                                                      \
        _Pragma("unroll")                                                              \
        for (int p = 0; p < 2; p++) {                                                  \
            *((__half2*)&As_[(arow + p * 64) * APAD + c4])     = __floats2half2_rn(ra[p].x, ra[p].y); \
            *((__half2*)&As_[(arow + p * 64) * APAD + c4 + 2]) = __floats2half2_rn(ra[p].z, ra[p].w); \
        }                                                                              \
        _Pragma("unroll")                                                              \
        for (int p = 0; p < 4; p++) {                                                  \
            *((__half2*)&Bs_[(brow + p * 64) * APAD + c4])     = __floats2half2_rn(rbw[p].x, rbw[p].y); \
            *((__half2*)&Bs_[(brow + p * 64) * APAD + c4 + 2]) = __floats2half2_rn(rbw[p].z, rbw[p].w); \
        }                                                                              \
    }

    LD_CHUNK(0);
    ST_CHUNK(0);
    __syncthreads();

    for (int kc = 0; kc < 64; kc++) {
        if (kc < 63) LD_CHUNK((kc + 1) * 16);

        const __half* As = sm + (kc & 1) * BUFSZ;
        const __half* Bs = As + ABUF;

        wmma::fragment<wmma::matrix_b, 16, 16, 16, __half, wmma::col_major> b[4];
#pragma unroll
        for (int j = 0; j < 4; j++)
            wmma::load_matrix_sync(b[j], &Bs[(wn * 64 + j * 16) * APAD], APAD);
#pragma unroll
        for (int i = 0; i < 4; i++) {
            wmma::fragment<wmma::matrix_a, 16, 16, 16, __half, wmma::row_major> a;
            wmma::load_matrix_sync(a, &As[(wm * 64 + i * 16) * APAD], APAD);
#pragma unroll
            for (int j = 0; j < 4; j++)
                wmma::mma_sync(acc[i][j], a, b[j], acc[i][j]);
        }

        if (kc < 63) ST_CHUNK((kc + 1) & 1);
        __syncthreads();
    }
#undef LD_CHUNK
#undef ST_CHUNK

    // Epilogue: per fm-block, stage warp's 16x64 through smem (ldm 68 floats
    // = 272B, 16B multiple), add bias, store. 8 warps x 1088 floats = 34.8KB.
    float* stg = reinterpret_cast<float*>(sm) + warp * 1088;
    const int n0 = nBase + wn * 64 + lane;
    const float bv0 = bvec[n0];
    const float bv1 = bvec[n0 + 32];
#pragma unroll
    for (int fm = 0; fm < 4; fm++) {
        __syncwarp();
#pragma unroll
        for (int fn = 0; fn < 4; fn++)
            wmma::store_matrix_sync(&stg[fn * 16], acc[fm][fn], 68, wmma::mem_row_major);
        __syncwarp();
#pragma unroll
        for (int r = 0; r < 16; r++) {
            const int m = mBase + wm * 64 + fm * 16 + r;
            float v0 = stg[r * 68 + lane] + bv0;
            float v1 = stg[r * 68 + lane + 32] + bv1;
            if (SPLIT) {
                const int b = m >> 9, i = m & 511;
                const int hh0 = n0 >> 6, d0 = n0 & 63;
                const int hh1 = (n0 + 32) >> 6, d1 = (n0 + 32) & 63;
                Y[(((size_t)(b * HH + hh0)) * NN + i) * DK + d0] = (YT)__float2half(v0);
                Y[(((size_t)(b * HH + hh1)) * NN + i) * DK + d1] = (YT)__float2half(v1);
            } else {
                ((float*)Y)[(size_t)m * DM + n0] = v0;
                ((float*)Y)[(size_t)m * DM + n0 + 32] = v1;
            }
        }
    }
}

__global__ void __launch_bounds__(256, 1) qkv_proj_kernel(QKVArgs args)
{
    __shared__ __align__(16) __half sm[2 * BUFSZ];   // 36 KB
    const int z = blockIdx.z;
    proj_body<true, __half>(args.X[z], args.W[z], args.bv[z], args.Y[z],
                            blockIdx.x * 128, blockIdx.y * 256, sm);
}

__global__ void __launch_bounds__(256, 1) out_proj_kernel(
    const float* __restrict__ X, const float* __restrict__ W,
    const float* __restrict__ bvec, float* __restrict__ Y)
{
    __shared__ __align__(16) __half sm[2 * BUFSZ];
    proj_body<false, float>(X, W, bvec, Y, blockIdx.x * 128, blockIdx.y * 256, sm);
}

// ---------------------------------------------------------------------------
// Fused attention, fp16 MMA: per CTA = (b,h, 64 q-rows), 4 warps.
// Bias/mask/O streams fully vectorized (float4/int4): lane -> 4 consecutive
// cols, 2 rows per iteration -> 4x fewer LDGs on the 268MB bias stream.
// Row sums: 8 per-thread accumulators, one 16-lane butterfly at the end.
// ---------------------------------------------------------------------------
__global__ void __launch_bounds__(128, 4) attn_kernel(
    const float* __restrict__ bias, const int* __restrict__ mask)
{
    extern __shared__ __align__(16) char smraw[];
    __half* Qh = (__half*)smraw;                 // 64 x 72
    __half* Kh = Qh + 64 * 72;                   // 64 x 72
    __half* Vh = Kh + 64 * 72;                   // 64 x 72
    __half* Ph = Vh + 64 * 72;                   // 64 x 72
    float*  Ss = (float*)(Ph + 64 * 72);         // 64 x 68
    float*  lrow = Ss + 64 * 68;                 // 64

    const int bh = blockIdx.y;
    const int b = bh >> 4;
    const int h = bh & 15;
    const int q0 = blockIdx.x * 64;
    const int tid = threadIdx.x;
    const int warp = tid >> 5;
    const int lane = tid & 31;
    const int m0 = warp * 16;
    const int c16 = lane & 15;      // float4 column group
    const int r2 = lane >> 4;       // row parity

    // Load Q tile (64x64 half)
    const __half* qptr = g_q + ((size_t)bh * NN + q0) * DK;
#pragma unroll
    for (int p = 0; p < 4; p++) {
        int e = tid + p * 128;
        int r = e >> 3, c8 = e & 7;
        *((uint4*)&Qh[r * 72 + c8 * 8]) = ((const uint4*)qptr)[r * 8 + c8];
    }

    wmma::fragment<wmma::accumulator, 16, 16, 16, float> o_acc[4];
#pragma unroll
    for (int t = 0; t < 4; t++) wmma::fill_fragment(o_acc[t], 0.0f);

    float rsum[8];
#pragma unroll
    for (int r = 0; r < 8; r++) rsum[r] = 0.0f;

    __syncthreads();

    for (int kt = 0; kt < 8; kt++) {
        const int k0 = kt * 64;
        const __half* kptr = g_k + ((size_t)bh * NN + k0) * DK;
        const __half* vptr = g_v + ((size_t)bh * NN + k0) * DK;
#pragma unroll
        for (int p = 0; p < 4; p++) {
            int e = tid + p * 128;
            int r = e >> 3, c8 = e & 7;
            *((uint4*)&Kh[r * 72 + c8 * 8]) = ((const uint4*)kptr)[r * 8 + c8];
            *((uint4*)&Vh[r * 72 + c8 * 8]) = ((const uint4*)vptr)[r * 8 + c8];
        }
        __syncthreads();

        // S strip (16 x 64) per warp, fp16 m16n16k16
        {
            wmma::fragment<wmma::accumulator, 16, 16, 16, float> s_acc[4];
#pragma unroll
            for (int t = 0; t < 4; t++) wmma::fill_fragment(s_acc[t], 0.0f);
#pragma unroll
            for (int kk = 0; kk < 4; kk++) {
                wmma::fragment<wmma::matrix_a, 16, 16, 16, __half, wmma::row_major> a;
                wmma::load_matrix_sync(a, &Qh[m0 * 72 + kk * 16], 72);
#pragma unroll
                for (int jt = 0; jt < 4; jt++) {
                    wmma::fragment<wmma::matrix_b, 16, 16, 16, __half, wmma::col_major> bf;
                    wmma::load_matrix_sync(bf, &Kh[(jt * 16) * 72 + kk * 16], 72);
                    wmma::mma_sync(s_acc[jt], a, bf, s_acc[jt]);
                }
            }
#pragma unroll
            for (int jt = 0; jt < 4; jt++)
                wmma::store_matrix_sync(&Ss[m0 * 68 + jt * 16], s_acc[jt], 68,
                                        wmma::mem_row_major);
        }
        __syncwarp();

        // Epilogue, vectorized: 2 rows per iter, float4 bias + int4 mask.
        {
#pragma unroll
            for (int rr = 0; rr < 8; rr++) {
                const int row = m0 + rr * 2 + r2;
                const float4 bb = *(const float4*)&bias[
                    ((size_t)bh * NN + (q0 + row)) * NN + k0 + c16 * 4];
                const int4 mm = *(const int4*)&mask[
                    ((size_t)b * NN + (q0 + row)) * NN + k0 + c16 * 4];
                float4 s = *(float4*)&Ss[row * 68 + c16 * 4];
                float p0 = (mm.x == 0) ? 0.0f : __expf(s.x * 0.125f + bb.x);
                float p1 = (mm.y == 0) ? 0.0f : __expf(s.y * 0.125f + bb.y);
                float p2 = (mm.z == 0) ? 0.0f : __expf(s.z * 0.125f + bb.z);
                float p3 = (mm.w == 0) ? 0.0f : __expf(s.w * 0.125f + bb.w);
                __half2 h01 = __floats2half2_rn(p0, p1);
                __half2 h23 = __floats2half2_rn(p2, p3);
                *(uint2*)&Ph[row * 72 + c16 * 4] =
                    make_uint2(*(unsigned*)&h01, *(unsigned*)&h23);
                rsum[rr] += __half2float(h01.x) + __half2float(h01.y) +
                            __half2float(h23.x) + __half2float(h23.y);
            }
        }
        __syncwarp();

        // O += P @ V
#pragma unroll
        for (int kk = 0; kk < 4; kk++) {
            wmma::fragment<wmma::matrix_a, 16, 16, 16, __half, wmma::row_major> a;
            wmma::load_matrix_sync(a, &Ph[m0 * 72 + kk * 16], 72);
#pragma unroll
            for (int dt = 0; dt < 4; dt++) {
                wmma::fragment<wmma::matrix_b, 16, 16, 16, __half, wmma::row_major> bf;
                wmma::load_matrix_sync(bf, &Vh[(kk * 16) * 72 + dt * 16], 72);
                wmma::mma_sync(o_acc[dt], a, bf, o_acc[dt]);
            }
        }
        __syncthreads();   // protect Kh/Vh before next tile's staging
    }

    // Reduce row sums within 16-lane groups, publish to lrow
#pragma unroll
    for (int rr = 0; rr < 8; rr++) {
        float s = rsum[rr];
#pragma unroll
        for (int o = 8; o; o >>= 1) s += __shfl_xor_sync(0xffffffffu, s, o);
        if (c16 == 0) lrow[m0 + rr * 2 + r2] = s;
    }

    // Store O strip via Ss, normalize, write ctx (vectorized float4)
#pragma unroll
    for (int dt = 0; dt < 4; dt++)
        wmma::store_matrix_sync(&Ss[m0 * 68 + dt * 16], o_acc[dt], 68,
                                wmma::mem_row_major);
    __syncwarp();
    {
#pragma unroll
        for (int rr = 0; rr < 8; rr++) {
            const int row = m0 + rr * 2 + r2;
            const float inv = 1.0f / lrow[row];
            float4 v = *(float4*)&Ss[row * 68 + c16 * 4];
            v.x *= inv; v.y *= inv; v.z *= inv; v.w *= inv;
            *(float4*)&g_ctx[((size_t)(b * NN) + q0 + row) * DM + h * DK + c16 * 4] = v;
        }
    }
}

// ---------------------------------------------------------------------------
extern "C" void kernel_launch(void* const* d_in, const int* in_sizes, int n_in,
                              void* d_out, int out_size)
{
    const float* query = (const float*)d_in[0];
    const float* key_  = (const float*)d_in[1];
    const float* value = (const float*)d_in[2];
    const float* abias = (const float*)d_in[3];
    const int*   mask  = (const int*)d_in[4];
    const float* Wq = (const float*)d_in[5];
    const float* bq = (const float*)d_in[6];
    const float* Wk = (const float*)d_in[7];
    const float* bk = (const float*)d_in[8];
    const float* Wv = (const float*)d_in[9];
    const float* bv = (const float*)d_in[10];
    const float* Wo = (const float*)d_in[11];
    const float* bo = (const float*)d_in[12];
    float* out = (float*)d_out;

    __half *pq, *pk, *pv;
    float *pctx;
    cudaGetSymbolAddress((void**)&pq, g_q);
    cudaGetSymbolAddress((void**)&pk, g_k);
    cudaGetSymbolAddress((void**)&pv, g_v);
    cudaGetSymbolAddress((void**)&pctx, g_ctx);

    // attn smem: 4*(64*72)*2 + 64*68*4 + 64*4 = 54528 B
    const int ATTN_SMEM = 4 * (64 * 72) * 2 + 64 * 68 * 4 + 64 * 4;
    cudaFuncSetAttribute(attn_kernel, cudaFuncAttributeMaxDynamicSharedMemorySize,
                         ATTN_SMEM);

    QKVArgs args;
    args.X[0] = query; args.X[1] = key_; args.X[2] = value;
    args.W[0] = Wq;    args.W[1] = Wk;   args.W[2] = Wv;
    args.bv[0] = bq;   args.bv[1] = bk;  args.bv[2] = bv;
    args.Y[0] = pq;    args.Y[1] = pk;   args.Y[2] = pv;

    dim3 qkvgrid(MTOT / 128, DM / 256, 3);
    qkv_proj_kernel<<<qkvgrid, 256>>>(args);

    dim3 agrid(NN / 64, BB * HH);
    attn_kernel<<<agrid, 128, ATTN_SMEM>>>(abias, mask);

    dim3 pgrid(MTOT / 128, DM / 256);
    out_proj_kernel<<<pgrid, 256>>>(pctx, Wo, bo, out);
}

// round 12
// speedup vs baseline: 1.1722x; 1.1722x over previous
#include <cuda_runtime.h>
#include <cuda_fp16.h>
#include <mma.h>

using namespace nvcuda;

// Problem constants
#define BB 16
#define NN 512
#define HH 16
#define DK 64
#define DM 1024
#define MTOT (BB * NN)   // 8192

// Scratch (allocation-free rule: __device__ globals)
__device__ __half g_q[BB * HH * NN * DK];
__device__ __half g_k[BB * HH * NN * DK];
__device__ __half g_v[BB * HH * NN * DK];
__device__ __half g_ctx[MTOT * DM];
__device__ __half g_w[4 * DM * DM];      // fp16 copies of Wq,Wk,Wv,Wo

struct QKVArgs {
    const float*  X[3];
    const __half* W[3];
    const float*  bv[3];
    __half*       Y[3];
};

__device__ __forceinline__ void cp16(void* dst_smem, const void* src) {
    unsigned d = (unsigned)__cvta_generic_to_shared(dst_smem);
    asm volatile("cp.async.ca.shared.global [%0], [%1], 16;" :: "r"(d), "l"(src));
}
__device__ __forceinline__ void cp_commit() { asm volatile("cp.async.commit_group;"); }
__device__ __forceinline__ void cp_wait0()  { asm volatile("cp.async.wait_group 0;"); }

// ---------------------------------------------------------------------------
// Weight fp32 -> fp16 conversion (grid-stride, float4 -> 4 halves)
// ---------------------------------------------------------------------------
__global__ void cvt_kernel(const float* __restrict__ src, __half* __restrict__ dst,
                           int n4)
{
    for (int i = blockIdx.x * blockDim.x + threadIdx.x; i < n4;
         i += gridDim.x * blockDim.x) {
        float4 v = ((const float4*)src)[i];
        __half2 h01 = __floats2half2_rn(v.x, v.y);
        __half2 h23 = __floats2half2_rn(v.z, v.w);
        *(uint2*)&dst[i * 4] = make_uint2(*(unsigned*)&h01, *(unsigned*)&h23);
    }
}

// ---------------------------------------------------------------------------
// QKV projection: Y = X @ W^T + b, head-split fp16 output.
// Block 128x128, 8 warps (2m x 4n), warp tile 64x32, fp16 HMMA m16n16k16.
// K-chunk 32, double-buffered. A (fp32 X): register-staged + cvt (as R10).
// B (fp16 W): cp.async straight into smem — no regs, no cvt, half the bytes.
// smem per buffer: A 128x40 + B 128x40 halves; 2 buffers = 40 KB.
// ---------------------------------------------------------------------------
#define PST 40
#define PBUF (128 * PST)            // halves per tile
#define PBUF2 (2 * PBUF)            // halves per buffer (A+B)

__global__ void __launch_bounds__(256, 2) qkv_proj_kernel(QKVArgs args)
{
    __shared__ __align__(16) __half sm[2 * PBUF2];   // 40 KB

    const int z = blockIdx.z;
    const float*  __restrict__ X = args.X[z];
    const __half* __restrict__ W = args.W[z];
    const float*  __restrict__ bvec = args.bv[z];
    __half* __restrict__ Y = args.Y[z];

    const int tid = threadIdx.x;
    const int warp = tid >> 5;
    const int lane = tid & 31;
    const int wm = warp & 1;
    const int wn = warp >> 1;
    const int mBase = blockIdx.x * 128;
    const int nBase = blockIdx.y * 128;

    wmma::fragment<wmma::accumulator, 16, 16, 16, float> acc[4][2];
#pragma unroll
    for (int i = 0; i < 4; i++)
#pragma unroll
        for (int j = 0; j < 2; j++) wmma::fill_fragment(acc[i][j], 0.0f);

    float4 ra[4];
    const int srow = tid >> 3;          // 0..31 (+p*32)
    const int scol = (tid & 7) * 4;     // 0..28
    const int brow = tid >> 1;          // 0..127
    const int bseg = (tid & 1) * 16;    // halves: 0 or 16 (2x16B per row of 64B)

#define LDA(K0)                                                                        \
    {                                                                                  \
        _Pragma("unroll")                                                              \
        for (int p = 0; p < 4; p++)                                                    \
            ra[p] = *((const float4*)&X[(size_t)(mBase + srow + p * 32) * DM + (K0) + scol]); \
    }

#define STA(NB)                                                                        \
    {                                                                                  \
        __half* As_ = sm + (NB) * PBUF2;                                               \
        _Pragma("unroll")                                                              \
        for (int p = 0; p < 4; p++) {                                                  \
            *((__half2*)&As_[(srow + p * 32) * PST + scol])     = __floats2half2_rn(ra[p].x, ra[p].y); \
            *((__half2*)&As_[(srow + p * 32) * PST + scol + 2]) = __floats2half2_rn(ra[p].z, ra[p].w); \
        }                                                                              \
    }

#define CPB(K0, NB)                                                                    \
    {                                                                                  \
        __half* Bs_ = sm + (NB) * PBUF2 + PBUF;                                        \
        cp16(&Bs_[brow * PST + bseg], &W[(size_t)(nBase + brow) * DM + (K0) + bseg]);  \
        cp16(&Bs_[brow * PST + bseg + 8],                                              \
             &W[(size_t)(nBase + brow) * DM + (K0) + bseg + 8]);                       \
    }

    CPB(0, 0); cp_commit();
    LDA(0); STA(0);
    cp_wait0();
    __syncthreads();

    for (int kc = 0; kc < 32; kc++) {
        if (kc < 31) {
            CPB((kc + 1) * 32, (kc + 1) & 1); cp_commit();
            LDA((kc + 1) * 32);
        }

        const __half* As = sm + (kc & 1) * PBUF2;
        const __half* Bs = As + PBUF;
#pragma unroll
        for (int kk = 0; kk < 2; kk++) {
            wmma::fragment<wmma::matrix_a, 16, 16, 16, __half, wmma::row_major> a[4];
#pragma unroll
            for (int i = 0; i < 4; i++)
                wmma::load_matrix_sync(a[i], &As[(wm * 64 + i * 16) * PST + kk * 16], PST);
            wmma::fragment<wmma::matrix_b, 16, 16, 16, __half, wmma::col_major> b[2];
#pragma unroll
            for (int j = 0; j < 2; j++)
                wmma::load_matrix_sync(b[j], &Bs[(wn * 32 + j * 16) * PST + kk * 16], PST);
#pragma unroll
            for (int i = 0; i < 4; i++)
#pragma unroll
                for (int j = 0; j < 2; j++)
                    wmma::mma_sync(acc[i][j], a[i], b[j], acc[i][j]);
        }

        if (kc < 31) { STA((kc + 1) & 1); cp_wait0(); }
        __syncthreads();
    }
#undef LDA
#undef STA
#undef CPB

    // Epilogue: stage 16x32 fp32 per warp (ldm 36 = 144B), add bias,
    // write head-split fp16.
    float* stg = reinterpret_cast<float*>(sm) + warp * 576;
    const int n = nBase + wn * 32 + lane;
    const float bv = bvec[n];
#pragma unroll
    for (int fm = 0; fm < 4; fm++) {
        __syncwarp();
#pragma unroll
        for (int fn = 0; fn < 2; fn++)
            wmma::store_matrix_sync(&stg[fn * 16], acc[fm][fn], 36, wmma::mem_row_major);
        __syncwarp();
#pragma unroll
        for (int r = 0; r < 16; r++) {
            float v = stg[r * 36 + lane] + bv;
            int m = mBase + wm * 64 + fm * 16 + r;
            int b = m >> 9, i = m & 511;
            int hh = n >> 6, d = n & 63;
            Y[(((size_t)(b * HH + hh)) * NN + i) * DK + d] = __float2half(v);
        }
    }
}

// ---------------------------------------------------------------------------
// Output projection: out = ctx(fp16) @ Wo(fp16)^T + bo, fp32 out.
// Both operands cp.async — no register staging at all.
// ---------------------------------------------------------------------------
__global__ void __launch_bounds__(256, 2) out_proj_kernel(
    const __half* __restrict__ X, const __half* __restrict__ W,
    const float* __restrict__ bvec, float* __restrict__ Y)
{
    __shared__ __align__(16) __half sm[2 * PBUF2];

    const int tid = threadIdx.x;
    const int warp = tid >> 5;
    const int lane = tid & 31;
    const int wm = warp & 1;
    const int wn = warp >> 1;
    const int mBase = blockIdx.x * 128;
    const int nBase = blockIdx.y * 128;

    wmma::fragment<wmma::accumulator, 16, 16, 16, float> acc[4][2];
#pragma unroll
    for (int i = 0; i < 4; i++)
#pragma unroll
        for (int j = 0; j < 2; j++) wmma::fill_fragment(acc[i][j], 0.0f);

    const int brow = tid >> 1;
    const int bseg = (tid & 1) * 16;

#define CPAB(K0, NB)                                                                   \
    {                                                                                  \
        __half* As_ = sm + (NB) * PBUF2;                                               \
        __half* Bs_ = As_ + PBUF;                                                      \
        cp16(&As_[brow * PST + bseg], &X[(size_t)(mBase + brow) * DM + (K0) + bseg]);  \
        cp16(&As_[brow * PST + bseg + 8],                                              \
             &X[(size_t)(mBase + brow) * DM + (K0) + bseg + 8]);                       \
        cp16(&Bs_[brow * PST + bseg], &W[(size_t)(nBase + brow) * DM + (K0) + bseg]);  \
        cp16(&Bs_[brow * PST + bseg + 8],                                              \
             &W[(size_t)(nBase + brow) * DM + (K0) + bseg + 8]);                       \
    }

    CPAB(0, 0); cp_commit();
    cp_wait0();
    __syncthreads();

    for (int kc = 0; kc < 32; kc++) {
        if (kc < 31) { CPAB((kc + 1) * 32, (kc + 1) & 1); cp_commit(); }

        const __half* As = sm + (kc & 1) * PBUF2;
        const __half* Bs = As + PBUF;
#pragma unroll
        for (int kk = 0; kk < 2; kk++) {
            wmma::fragment<wmma::matrix_a, 16, 16, 16, __half, wmma::row_major> a[4];
#pragma unroll
            for (int i = 0; i < 4; i++)
                wmma::load_matrix_sync(a[i], &As[(wm * 64 + i * 16) * PST + kk * 16], PST);
            wmma::fragment<wmma::matrix_b, 16, 16, 16, __half, wmma::col_major> b[2];
#pragma unroll
            for (int j = 0; j < 2; j++)
                wmma::load_matrix_sync(b[j], &Bs[(wn * 32 + j * 16) * PST + kk * 16], PST);
#pragma unroll
            for (int i = 0; i < 4; i++)
#pragma unroll
                for (int j = 0; j < 2; j++)
                    wmma::mma_sync(acc[i][j], a[i], b[j], acc[i][j]);
        }

        if (kc < 31) cp_wait0();
        __syncthreads();
    }
#undef CPAB

    float* stg = reinterpret_cast<float*>(sm) + warp * 576;
    const int n = nBase + wn * 32 + lane;
    const float bv = bvec[n];
#pragma unroll
    for (int fm = 0; fm < 4; fm++) {
        __syncwarp();
#pragma unroll
        for (int fn = 0; fn < 2; fn++)
            wmma::store_matrix_sync(&stg[fn * 16], acc[fm][fn], 36, wmma::mem_row_major);
        __syncwarp();
#pragma unroll
        for (int r = 0; r < 16; r++) {
            float v = stg[r * 36 + lane] + bv;
            int m = mBase + wm * 64 + fm * 16 + r;
            Y[(size_t)m * DM + n] = v;
        }
    }
}

// ---------------------------------------------------------------------------
// Fused attention, fp16 MMA, vectorized epilogue (R11 version), ctx fp16.
// ---------------------------------------------------------------------------
__global__ void __launch_bounds__(128, 4) attn_kernel(
    const float* __restrict__ bias, const int* __restrict__ mask)
{
    extern __shared__ __align__(16) char smraw[];
    __half* Qh = (__half*)smraw;                 // 64 x 72
    __half* Kh = Qh + 64 * 72;                   // 64 x 72
    __half* Vh = Kh + 64 * 72;                   // 64 x 72
    __half* Ph = Vh + 64 * 72;                   // 64 x 72
    float*  Ss = (float*)(Ph + 64 * 72);         // 64 x 68
    float*  lrow = Ss + 64 * 68;                 // 64

    const int bh = blockIdx.y;
    const int b = bh >> 4;
    const int h = bh & 15;
    const int q0 = blockIdx.x * 64;
    const int tid = threadIdx.x;
    const int warp = tid >> 5;
    const int lane = tid & 31;
    const int m0 = warp * 16;
    const int c16 = lane & 15;
    const int r2 = lane >> 4;

    const __half* qptr = g_q + ((size_t)bh * NN + q0) * DK;
#pragma unroll
    for (int p = 0; p < 4; p++) {
        int e = tid + p * 128;
        int r = e >> 3, c8 = e & 7;
        *((uint4*)&Qh[r * 72 + c8 * 8]) = ((const uint4*)qptr)[r * 8 + c8];
    }

    wmma::fragment<wmma::accumulator, 16, 16, 16, float> o_acc[4];
#pragma unroll
    for (int t = 0; t < 4; t++) wmma::fill_fragment(o_acc[t], 0.0f);

    float rsum[8];
#pragma unroll
    for (int r = 0; r < 8; r++) rsum[r] = 0.0f;

    __syncthreads();

    for (int kt = 0; kt < 8; kt++) {
        const int k0 = kt * 64;
        const __half* kptr = g_k + ((size_t)bh * NN + k0) * DK;
        const __half* vptr = g_v + ((size_t)bh * NN + k0) * DK;
#pragma unroll
        for (int p = 0; p < 4; p++) {
            int e = tid + p * 128;
            int r = e >> 3, c8 = e & 7;
            *((uint4*)&Kh[r * 72 + c8 * 8]) = ((const uint4*)kptr)[r * 8 + c8];
            *((uint4*)&Vh[r * 72 + c8 * 8]) = ((const uint4*)vptr)[r * 8 + c8];
        }
        __syncthreads();

        {
            wmma::fragment<wmma::accumulator, 16, 16, 16, float> s_acc[4];
#pragma unroll
            for (int t = 0; t < 4; t++) wmma::fill_fragment(s_acc[t], 0.0f);
#pragma unroll
            for (int kk = 0; kk < 4; kk++) {
                wmma::fragment<wmma::matrix_a, 16, 16, 16, __half, wmma::row_major> a;
                wmma::load_matrix_sync(a, &Qh[m0 * 72 + kk * 16], 72);
#pragma unroll
                for (int jt = 0; jt < 4; jt++) {
                    wmma::fragment<wmma::matrix_b, 16, 16, 16, __half, wmma::col_major> bf;
                    wmma::load_matrix_sync(bf, &Kh[(jt * 16) * 72 + kk * 16], 72);
                    wmma::mma_sync(s_acc[jt], a, bf, s_acc[jt]);
                }
            }
#pragma unroll
            for (int jt = 0; jt < 4; jt++)
                wmma::store_matrix_sync(&Ss[m0 * 68 + jt * 16], s_acc[jt], 68,
                                        wmma::mem_row_major);
        }
        __syncwarp();

        {
#pragma unroll
            for (int rr = 0; rr < 8; rr++) {
                const int row = m0 + rr * 2 + r2;
                const float4 bb = *(const float4*)&bias[
                    ((size_t)bh * NN + (q0 + row)) * NN + k0 + c16 * 4];
                const int4 mm = *(const int4*)&mask[
                    ((size_t)b * NN + (q0 + row)) * NN + k0 + c16 * 4];
                float4 s = *(float4*)&Ss[row * 68 + c16 * 4];
                float p0 = (mm.x == 0) ? 0.0f : __expf(s.x * 0.125f + bb.x);
                float p1 = (mm.y == 0) ? 0.0f : __expf(s.y * 0.125f + bb.y);
                float p2 = (mm.z == 0) ? 0.0f : __expf(s.z * 0.125f + bb.z);
                float p3 = (mm.w == 0) ? 0.0f : __expf(s.w * 0.125f + bb.w);
                __half2 h01 = __floats2half2_rn(p0, p1);
                __half2 h23 = __floats2half2_rn(p2, p3);
                *(uint2*)&Ph[row * 72 + c16 * 4] =
                    make_uint2(*(unsigned*)&h01, *(unsigned*)&h23);
                rsum[rr] += __half2float(h01.x) + __half2float(h01.y) +
                            __half2float(h23.x) + __half2float(h23.y);
            }
        }
        __syncwarp();

#pragma unroll
        for (int kk = 0; kk < 4; kk++) {
            wmma::fragment<wmma::matrix_a, 16, 16, 16, __half, wmma::row_major> a;
            wmma::load_matrix_sync(a, &Ph[m0 * 72 + kk * 16], 72);
#pragma unroll
            for (int dt = 0; dt < 4; dt++) {
                wmma::fragment<wmma::matrix_b, 16, 16, 16, __half, wmma::row_major> bf;
                wmma::load_matrix_sync(bf, &Vh[(kk * 16) * 72 + dt * 16], 72);
                wmma::mma_sync(o_acc[dt], a, bf, o_acc[dt]);
            }
        }
        __syncthreads();
    }

#pragma unroll
    for (int rr = 0; rr < 8; rr++) {
        float s = rsum[rr];
#pragma unroll
        for (int o = 8; o; o >>= 1) s += __shfl_xor_sync(0xffffffffu, s, o);
        if (c16 == 0) lrow[m0 + rr * 2 + r2] = s;
    }

#pragma unroll
    for (int dt = 0; dt < 4; dt++)
        wmma::store_matrix_sync(&Ss[m0 * 68 + dt * 16], o_acc[dt], 68,
                                wmma::mem_row_major);
    __syncwarp();
    {
#pragma unroll
        for (int rr = 0; rr < 8; rr++) {
            const int row = m0 + rr * 2 + r2;
            const float inv = 1.0f / lrow[row];
            float4 v = *(float4*)&Ss[row * 68 + c16 * 4];
            __half2 h01 = __floats2half2_rn(v.x * inv, v.y * inv);
            __half2 h23 = __floats2half2_rn(v.z * inv, v.w * inv);
            *(uint2*)&g_ctx[((size_t)(b * NN) + q0 + row) * DM + h * DK + c16 * 4] =
                make_uint2(*(unsigned*)&h01, *(unsigned*)&h23);
        }
    }
}

// ---------------------------------------------------------------------------
extern "C" void kernel_launch(void* const* d_in, const int* in_sizes, int n_in,
                              void* d_out, int out_size)
{
    const float* query = (const float*)d_in[0];
    const float* key_  = (const float*)d_in[1];
    const float* value = (const float*)d_in[2];
    const float* abias = (const float*)d_in[3];
    const int*   mask  = (const int*)d_in[4];
    const float* Wq = (const float*)d_in[5];
    const float* bq = (const float*)d_in[6];
    const float* Wk = (const float*)d_in[7];
    const float* bk = (const float*)d_in[8];
    const float* Wv = (const float*)d_in[9];
    const float* bv = (const float*)d_in[10];
    const float* Wo = (const float*)d_in[11];
    const float* bo = (const float*)d_in[12];
    float* out = (float*)d_out;

    __half *pq, *pk, *pv, *pctx, *pw;
    cudaGetSymbolAddress((void**)&pq, g_q);
    cudaGetSymbolAddress((void**)&pk, g_k);
    cudaGetSymbolAddress((void**)&pv, g_v);
    cudaGetSymbolAddress((void**)&pctx, g_ctx);
    cudaGetSymbolAddress((void**)&pw, g_w);

    // Convert the four weight matrices to fp16 (1M elems = 256K float4 each)
    const float* wsrc[4] = {Wq, Wk, Wv, Wo};
    for (int i = 0; i < 4; i++)
        cvt_kernel<<<256, 256>>>(wsrc[i], pw + (size_t)i * DM * DM, DM * DM / 4);

    // attn smem: 4*(64*72)*2 + 64*68*4 + 64*4 = 54528 B
    const int ATTN_SMEM = 4 * (64 * 72) * 2 + 64 * 68 * 4 + 64 * 4;
    cudaFuncSetAttribute(attn_kernel, cudaFuncAttributeMaxDynamicSharedMemorySize,
                         ATTN_SMEM);

    QKVArgs args;
    args.X[0] = query; args.X[1] = key_; args.X[2] = value;
    args.W[0] = pw;    args.W[1] = pw + (size_t)DM * DM;
    args.W[2] = pw + (size_t)2 * DM * DM;
    args.bv[0] = bq;   args.bv[1] = bk;  args.bv[2] = bv;
    args.Y[0] = pq;    args.Y[1] = pk;   args.Y[2] = pv;

    dim3 qkvgrid(MTOT / 128, DM / 128, 3);
    qkv_proj_kernel<<<qkvgrid, 256>>>(args);

    dim3 agrid(NN / 64, BB * HH);
    attn_kernel<<<agrid, 128, ATTN_SMEM>>>(abias, mask);

    dim3 pgrid(MTOT / 128, DM / 128);
    out_proj_kernel<<<pgrid, 256>>>(pctx, pw + (size_t)3 * DM * DM, bo, out);
}